// round 4
// baseline (speedup 1.0000x reference)
#include <cuda_runtime.h>

// Problem shapes (fixed by the dataset)
#define BB 16
#define TT 256
#define NPTS 2048
#define TC 8                 // chunks over T
#define FR (TT / TC)         // 32 frames per chunk
#define NSLOTS (BB * TC)     // 128
#define NSTAT 13             // cnt, 3x sum(p), 3x sum(p^2), 3x sum(g), 3x sum(g^2)

// Scratch (device globals only; no runtime allocation)
__device__ float  g_scratch[NSLOTS * NSTAT * NPTS];   // ~13.6 MB
__device__ float  g_reduced[NSTAT * NPTS];
__device__ double g_recon, g_temp, g_nvel, g_ident, g_nvis;

__global__ void k_zero() {
    g_recon = 0.0; g_temp = 0.0; g_nvel = 0.0; g_ident = 0.0; g_nvis = 0.0;
}

// ---------------------------------------------------------------------------
// K1: single streaming pass.
// thread <-> (slot = b*TC + tc, n). Consecutive threads have consecutive n
// => fully coalesced loads. Each thread walks FR frames keeping the previous
// frame in registers for the velocity term.
// ---------------------------------------------------------------------------
__global__ __launch_bounds__(256)
void k_main(const float* __restrict__ pred, const float* __restrict__ gt,
            const float* __restrict__ vis) {
    unsigned tid  = blockIdx.x * 256u + threadIdx.x;
    unsigned n    = tid % NPTS;
    unsigned slot = tid / NPTS;          // 0..127
    unsigned b    = slot / TC;
    unsigned tc   = slot % TC;
    unsigned t0   = tc * FR;

    float cnt = 0.f;
    float spx0=0.f,spx1=0.f,spx2=0.f, spq0=0.f,spq1=0.f,spq2=0.f;
    float sgx0=0.f,sgx1=0.f,sgx2=0.f, sgq0=0.f,sgq1=0.f,sgq2=0.f;
    float recon = 0.f, temporal = 0.f, nvel = 0.f;
    float pp0=0.f,pp1=0.f,pp2=0.f, pg0=0.f,pg1=0.f,pg2=0.f, pm=0.f;

    unsigned rowbase = (b * TT + t0) * NPTS + n;

    if (t0 > 0) {  // preload frame t0-1 for the velocity term
        unsigned pr = rowbase - NPTS;
        unsigned pe = pr * 3u;
        pp0 = pred[pe]; pp1 = pred[pe + 1]; pp2 = pred[pe + 2];
        pg0 = gt[pe];   pg1 = gt[pe + 1];   pg2 = gt[pe + 2];
        pm  = (vis[pr] > 0.5f) ? 1.f : 0.f;
    }

    #pragma unroll 4
    for (unsigned i = 0; i < FR; i++) {
        unsigned t    = t0 + i;
        unsigned ridx = rowbase + i * NPTS;
        unsigned e    = ridx * 3u;
        float p0 = pred[e], p1 = pred[e + 1], p2 = pred[e + 2];
        float g0 = gt[e],   g1 = gt[e + 1],   g2 = gt[e + 2];
        float m  = (vis[ridx] > 0.5f) ? 1.f : 0.f;

        cnt += m;
        float d0 = p0 - g0, d1 = p1 - g1, d2 = p2 - g2;
        recon += m * (d0 * d0 + d1 * d1 + 2.f * d2 * d2);

        spx0 += m * p0; spq0 += m * p0 * p0;
        spx1 += m * p1; spq1 += m * p1 * p1;
        spx2 += m * p2; spq2 += m * p2 * p2;
        sgx0 += m * g0; sgq0 += m * g0 * g0;
        sgx1 += m * g1; sgq1 += m * g1 * g1;
        sgx2 += m * g2; sgq2 += m * g2 * g2;

        if (t > 0) {
            float vm = m * pm;
            float e0 = (p0 - pp0) - (g0 - pg0);
            float e1 = (p1 - pp1) - (g1 - pg1);
            float e2 = (p2 - pp2) - (g2 - pg2);
            temporal += vm * (e0 * e0 + e1 * e1 + e2 * e2);
            nvel     += vm;
        }
        pp0 = p0; pp1 = p1; pp2 = p2;
        pg0 = g0; pg1 = g1; pg2 = g2;
        pm  = m;
    }

    // per-point partials -> scratch (coalesced over n)
    float* s = g_scratch + (size_t)slot * (NSTAT * NPTS) + n;
    s[0]          = cnt;
    s[1  * NPTS]  = spx0;  s[2  * NPTS] = spx1;  s[3  * NPTS] = spx2;
    s[4  * NPTS]  = spq0;  s[5  * NPTS] = spq1;  s[6  * NPTS] = spq2;
    s[7  * NPTS]  = sgx0;  s[8  * NPTS] = sgx1;  s[9  * NPTS] = sgx2;
    s[10 * NPTS]  = sgq0;  s[11 * NPTS] = sgq1;  s[12 * NPTS] = sgq2;

    // block-reduce recon / temporal / nvel, one double atomic each per block
    __shared__ float sm[3][8];
    float wr = recon, wt = temporal, wv = nvel;
    #pragma unroll
    for (int o = 16; o > 0; o >>= 1) {
        wr += __shfl_down_sync(0xffffffffu, wr, o);
        wt += __shfl_down_sync(0xffffffffu, wt, o);
        wv += __shfl_down_sync(0xffffffffu, wv, o);
    }
    int lane = threadIdx.x & 31, wid = threadIdx.x >> 5;
    if (lane == 0) { sm[0][wid] = wr; sm[1][wid] = wt; sm[2][wid] = wv; }
    __syncthreads();
    if (wid < 3 && lane < 8) {
        float v = sm[wid][lane];
        #pragma unroll
        for (int o = 4; o > 0; o >>= 1) v += __shfl_down_sync(0xffu, v, o);
        if (lane == 0) {
            if      (wid == 0) atomicAdd(&g_recon, (double)v);
            else if (wid == 1) atomicAdd(&g_temp,  (double)v);
            else               atomicAdd(&g_nvel,  (double)v);
        }
    }
}

// ---------------------------------------------------------------------------
// K2: reduce the 128 slots per (stat, n). Consecutive threads = consecutive n
// => each slot-iteration is a coalesced 128B-line load.
// ---------------------------------------------------------------------------
__global__ __launch_bounds__(256)
void k_reduce_slots() {
    unsigned tid = blockIdx.x * 256u + threadIdx.x;   // stat*NPTS + n
    if (tid >= NSTAT * NPTS) return;
    float s = 0.f;
    #pragma unroll 8
    for (int slot = 0; slot < NSLOTS; slot++)
        s += g_scratch[(size_t)slot * (NSTAT * NPTS) + tid];
    g_reduced[tid] = s;
}

// ---------------------------------------------------------------------------
// K3: per-point variance ratio + global identity / num_visible reduction
// ---------------------------------------------------------------------------
__global__ __launch_bounds__(256)
void k_identity() {
    unsigned n = blockIdx.x * 256u + threadIdx.x;
    float contrib = 0.f, cnt = 0.f;
    if (n < NPTS) {
        cnt = g_reduced[n];
        float dm = fmaxf(cnt, 1.f);
        float dv = fmaxf(cnt - 1.f, 1.f);
        float num = 0.f, den = 0.f;
        #pragma unroll
        for (int c = 0; c < 3; c++) {
            float sx = g_reduced[(1 + c) * NPTS + n];
            float sq = g_reduced[(4 + c) * NPTS + n];
            float mean = sx / dm;
            float pv = (sq - 2.f * mean * sx + cnt * mean * mean) / dv;
            float gx = g_reduced[(7 + c)  * NPTS + n];
            float gq = g_reduced[(10 + c) * NPTS + n];
            float gmean = gx / dm;
            float gv = (gq - 2.f * gmean * gx + cnt * gmean * gmean) / dv;
            num += fabsf(pv - gv);
            den += gv;
        }
        float vr = num / (den + 1e-6f);
        contrib = (cnt > 1.f) ? vr : 0.f;
    }
    __shared__ float sm[2][8];
    float wi = contrib, wc = cnt;
    #pragma unroll
    for (int o = 16; o > 0; o >>= 1) {
        wi += __shfl_down_sync(0xffffffffu, wi, o);
        wc += __shfl_down_sync(0xffffffffu, wc, o);
    }
    int lane = threadIdx.x & 31, wid = threadIdx.x >> 5;
    if (lane == 0) { sm[0][wid] = wi; sm[1][wid] = wc; }
    __syncthreads();
    if (wid < 2 && lane < 8) {
        float v = sm[wid][lane];
        #pragma unroll
        for (int o = 4; o > 0; o >>= 1) v += __shfl_down_sync(0xffu, v, o);
        if (lane == 0) {
            if (wid == 0) atomicAdd(&g_ident, (double)v);
            else          atomicAdd(&g_nvis,  (double)v);
        }
    }
}

// ---------------------------------------------------------------------------
// K4: final scalar math + adaptive re-weighting
// ---------------------------------------------------------------------------
__global__ void k_final(float* __restrict__ out) {
    double nvis = g_nvis;
    double nvel = g_nvel;
    float recon    = (nvis > 0.0) ? (float)(g_recon / fmax(nvis, 1.0)) : 0.f;
    float temporal = (nvel > 0.0) ? (float)(g_temp  / fmax(nvel, 1.0)) : 0.f;
    float identity = (float)(g_ident / (double)NPTS);

    float rl = recon, tl = temporal, il = identity;
    bool  all_pos = (rl > 0.f) && (tl > 0.f) && (il > 0.f);
    float mx     = fmaxf(fmaxf(rl, tl), il);
    float target = mx / 3.f;
    float thresh = 10.f * target;

    float rw = (all_pos && rl > thresh) ? 1.0f * target / fmaxf(rl, 1e-30f) : 1.0f;
    float tw = (all_pos && tl > thresh) ? 0.5f * target / fmaxf(tl, 1e-30f) : 0.5f;
    float iw = (all_pos && il > thresh) ? 0.1f * target / fmaxf(il, 1e-30f) : 0.1f;

    out[0] = rw * recon + tw * temporal + iw * identity;
    out[1] = recon;
    out[2] = temporal;
    out[3] = identity;
}

extern "C" void kernel_launch(void* const* d_in, const int* in_sizes, int n_in,
                              void* d_out, int out_size) {
    const float* pred = (const float*)d_in[0];
    const float* gt   = (const float*)d_in[1];
    const float* vis  = (const float*)d_in[2];
    float* out = (float*)d_out;

    k_zero<<<1, 1>>>();
    k_main<<<(BB * TC * NPTS) / 256, 256>>>(pred, gt, vis);
    k_reduce_slots<<<(NSTAT * NPTS + 255) / 256, 256>>>();
    k_identity<<<(NPTS + 255) / 256, 256>>>();
    k_final<<<1, 1>>>(out);
}